// round 13
// baseline (speedup 1.0000x reference)
#include <cuda_runtime.h>
#include <math.h>

#define BATCH 8
#define C     192
#define NH    6
#define CHD   32
#define HW    16384
#define IMG   128
#define T     4
#define STRIPS 32        // 128 / T

// ---------------- small device globals (~1.0 MiB total) ---------------------
__device__ float g_qsqp [NH * STRIPS * 32];
__device__ float g_ksqp [NH * STRIPS * 32];
__device__ float g_gramp[NH * STRIPS * 1024];
__device__ float g_qn[C];
__device__ float g_kn[C];
__device__ float g_attn[NH * 1024];               // softmaxed attn, [d*32+c]
__device__ float g_outsump[NH * STRIPS * 32];
__device__ float g_sigcm[C];
__device__ float g_sm[2 * HW];
__device__ float g_sigsp[HW];

__device__ __forceinline__ float gelu_f(float v) {
    return 0.5f * v * (1.f + erff(v * 0.70710678118654752f));
}

// ============================================================================
// Fused pass (512 threads): y = W_group(32ch)*x -> dw3x3(w_dw) -> epilogue.
// One block = one 4-row strip x one 32-channel group.
// EP 0: q -> S + qsq | EP 1: k -> Gram + ksq | EP 2: out (slow) | EP 3: v -> S
// ============================================================================
template<int EP>
__global__ void __launch_bounds__(512, 1) fused_k(
    const float* __restrict__ x, const float* __restrict__ wqkv,
    const float* __restrict__ wdw, float* __restrict__ S)
{
    extern __shared__ float sm[];
    float* Wt  = sm;                 // 6144
    float* Ys  = Wt + 6144;          // 24576 : 32ch x 768px
    float* zs  = Ys + 24576;         // 16384 : 32ch x 512px
    float* w9s = zs + 16384;         // 288
    float* extra = w9s + 288;        // EP1: qs[4096]; EP2: Ast[1024]+outws[512]

    const int tid = threadIdx.x;
    const int strip = blockIdx.x, g = blockIdx.y;
    const int qkvoff = (EP == 0) ? 0 : (EP == 1) ? C : 2 * C;
    const int cb = qkvoff + g * 32;
    const float* wb = wqkv + (size_t)cb * C;

    for (int i = tid; i < 6144; i += 512) {
        int c = i >> 5, j = i & 31;
        Wt[c * 32 + j] = wb[(size_t)j * C + c];
    }
    if (tid < 288) w9s[tid] = wdw[cb * 9 + tid];
    __syncthreads();

    const int R0 = strip * T;
    // ---- stage 1: GEMM y[32][768]; oh in 0..3, 8 channels each ----
    {
        int px = tid & 127, oh = tid >> 7;
        for (int px0 = 0; px0 < 768; px0 += 128) {
            int p = px0 + px;
            int er = R0 - 1 + (p >> 7);
            int col = p & 127;
            float acc[8];
#pragma unroll
            for (int j = 0; j < 8; j++) acc[j] = 0.f;
            if (er >= 0 && er < IMG) {
                const float* xp = x + er * IMG + col;
#pragma unroll 4
                for (int c = 0; c < C; c++) {
                    float xv = __ldg(xp + (size_t)c * HW);
                    const float4* wr = (const float4*)(Wt + c * 32 + oh * 8);
                    float4 w0 = wr[0], w1 = wr[1];
                    acc[0] += w0.x * xv; acc[1] += w0.y * xv;
                    acc[2] += w0.z * xv; acc[3] += w0.w * xv;
                    acc[4] += w1.x * xv; acc[5] += w1.y * xv;
                    acc[6] += w1.z * xv; acc[7] += w1.w * xv;
                }
            }
#pragma unroll
            for (int j = 0; j < 8; j++) Ys[(oh * 8 + j) * 768 + p] = acc[j];
        }
    }
    __syncthreads();

    // ---- stage 2: dw3x3 (w_dw) -> zs[32][512] ----
    for (int idx = tid; idx < 32 * 512; idx += 512) {
        int j = idx >> 9, p = idx & 511, r = p >> 7, xc = p & 127;
        const float* yr = Ys + j * 768;
        const float* w9 = w9s + j * 9;
        float a = 0.f;
#pragma unroll
        for (int dy = 0; dy < 3; dy++) {
            int base = (r + dy) * 128 + xc;
            if (xc > 0)   a += w9[dy * 3 + 0] * yr[base - 1];
                          a += w9[dy * 3 + 1] * yr[base];
            if (xc < 127) a += w9[dy * 3 + 2] * yr[base + 1];
        }
        zs[idx] = a;
    }
    __syncthreads();

    const int w = tid >> 5, lane = tid & 31;   // 16 warps

    if (EP == 0 || EP == 3) {
        for (int idx = tid; idx < 32 * 512; idx += 512) {
            int j = idx >> 9, p = idx & 511;
            S[(size_t)(g * 32 + j) * HW + strip * 512 + p] = zs[idx];
        }
    }
    if (EP == 0) {
#pragma unroll
        for (int m = 0; m < 2; m++) {
            int j = w * 2 + m;
            float s = 0.f;
            for (int t = 0; t < 16; t++) { float v = zs[j * 512 + lane + 32 * t]; s += v * v; }
#pragma unroll
            for (int off = 16; off > 0; off >>= 1) s += __shfl_down_sync(0xffffffffu, s, off);
            if (lane == 0) g_qsqp[(g * STRIPS + strip) * 32 + j] = s;
        }
    }

    if (EP == 1) {
        float* qs = extra;                     // 32 x 128 chunk of q
        int a_ = tid >> 4, b_ = tid & 15;      // 32 x 16; each does 1x2 tile
        float ga0 = 0.f, ga1 = 0.f;
        for (int ch = 0; ch < 4; ch++) {
            __syncthreads();
            for (int i = tid; i < 4096; i += 512) {
                int j = i >> 7, l = i & 127;
                qs[j * 128 + l] = S[(size_t)(g * 32 + j) * HW + strip * 512 + ch * 128 + l];
            }
            __syncthreads();
            const float* qp  = qs + a_ * 128;
            const float* k0p = zs + (2 * b_) * 512 + ch * 128;
            const float* k1p = zs + (2 * b_ + 1) * 512 + ch * 128;
#pragma unroll 4
            for (int l = 0; l < 128; l++) {
                float q0 = qp[l];
                ga0 += q0 * k0p[l]; ga1 += q0 * k1p[l];
            }
        }
        float* gp = g_gramp + (size_t)(g * STRIPS + strip) * 1024;
        gp[a_ * 32 + 2 * b_]     = ga0;
        gp[a_ * 32 + 2 * b_ + 1] = ga1;
#pragma unroll
        for (int m = 0; m < 2; m++) {
            int j = w * 2 + m;
            float s = 0.f;
            for (int t = 0; t < 16; t++) { float v = zs[j * 512 + lane + 32 * t]; s += v * v; }
#pragma unroll
            for (int off = 16; off > 0; off >>= 1) s += __shfl_down_sync(0xffffffffu, s, off);
            if (lane == 0) g_ksqp[(g * STRIPS + strip) * 32 + j] = s;
        }
    }

    if (EP == 2) {
        float* Ast = extra;                    // [d][c]
        float* outws = extra + 1024;           // 512
        for (int i = tid; i < 1024; i += 512) Ast[i] = g_attn[g * 1024 + i];
        __syncthreads();
        int p = tid;                           // 1 pixel per thread
        float acc[32];
#pragma unroll
        for (int c = 0; c < 32; c++) acc[c] = 0.f;
#pragma unroll 4
        for (int d = 0; d < 32; d++) {
            float vv = zs[d * 512 + p];
            const float4* ar = (const float4*)(Ast + d * 32);
#pragma unroll
            for (int q = 0; q < 8; q++) {
                float4 a4 = ar[q];
                acc[4 * q + 0] += a4.x * vv; acc[4 * q + 1] += a4.y * vv;
                acc[4 * q + 2] += a4.z * vv; acc[4 * q + 3] += a4.w * vv;
            }
        }
#pragma unroll
        for (int c = 0; c < 32; c++) {
            S[(size_t)(g * 32 + c) * HW + strip * 512 + p] = acc[c];
            float v = acc[c];
#pragma unroll
            for (int off = 16; off > 0; off >>= 1) v += __shfl_down_sync(0xffffffffu, v, off);
            if (lane == 0) { if (c == 0) {} outws[w * 32 + c] = v; }
        }
        __syncthreads();
        if (tid < 32) {
            float s = 0.f;
            for (int w2 = 0; w2 < 16; w2++) s += outws[w2 * 32 + tid];
            g_outsump[(g * STRIPS + strip) * 32 + tid] = s;
        }
    }
}

// ============================================================================
// Fast-path attention mix (512 threads): S = A · V per head + pooled partials.
// ============================================================================
__global__ void __launch_bounds__(512, 1) attnmix_k(
    const float* __restrict__ V, float* __restrict__ S)
{
    __shared__ float Ast[1024];
    __shared__ float outws[512];
    const int strip = blockIdx.x, h = blockIdx.y;
    const int tid = threadIdx.x;
    for (int i = tid; i < 1024; i += 512) Ast[i] = g_attn[h * 1024 + i];
    __syncthreads();
    const int w = tid >> 5, lane = tid & 31;
    int p = strip * 512 + tid;
    float acc[32];
#pragma unroll
    for (int c = 0; c < 32; c++) acc[c] = 0.f;
#pragma unroll 4
    for (int d = 0; d < 32; d++) {
        float vv = __ldg(V + (size_t)(h * 32 + d) * HW + p);
        const float4* ar = (const float4*)(Ast + d * 32);
#pragma unroll
        for (int q = 0; q < 8; q++) {
            float4 a4 = ar[q];
            acc[4 * q + 0] += a4.x * vv; acc[4 * q + 1] += a4.y * vv;
            acc[4 * q + 2] += a4.z * vv; acc[4 * q + 3] += a4.w * vv;
        }
    }
#pragma unroll
    for (int c = 0; c < 32; c++) {
        S[(size_t)(h * 32 + c) * HW + p] = acc[c];
        float v = acc[c];
#pragma unroll
        for (int off = 16; off > 0; off >>= 1) v += __shfl_down_sync(0xffffffffu, v, off);
        if (lane == 0) outws[w * 32 + c] = v;
    }
    __syncthreads();
    if (tid < 32) {
        float s = 0.f;
        for (int w2 = 0; w2 < 16; w2++) s += outws[w2 * 32 + tid];
        g_outsump[(h * STRIPS + strip) * 32 + tid] = s;
    }
}

// ============================================================================
// Fast-path conv branch from stored V (256 threads; memory-light).
// ============================================================================
template<int EP>
__global__ void __launch_bounds__(256, 1) convV_k(
    const float* __restrict__ V, const float* __restrict__ wdc,
    const float* __restrict__ bdc, const float* __restrict__ lnw,
    const float* __restrict__ lnb, float* __restrict__ S)
{
    extern __shared__ float sm[];
    float* cxs  = sm;               // 24576
    float* Vg   = cxs + 24576;      // 12288 : 32ch x 384px
    float* w9b  = Vg + 12288;       // 288
    float* mus  = w9b + 288;        // 128
    float* rss  = mus + 128;        // 128
    float* lnws = rss + 128;        // 192
    float* lnbs = lnws + 192;       // 192
    float* bds  = lnbs + 192;       // 192

    const int tid = threadIdx.x;
    const int R = blockIdx.x;
    if (tid < C) { lnws[tid] = lnw[tid]; lnbs[tid] = lnb[tid]; bds[tid] = bdc[tid]; }

    for (int grp = 0; grp < 6; grp++) {
        __syncthreads();
        for (int i = tid; i < 288; i += 256) w9b[i] = wdc[(grp * 32) * 9 + i];
        for (int idx = tid; idx < 32 * 384; idx += 256) {
            int ch = idx / 384, p = idx % 384, r = p >> 7, xc = p & 127;
            int vrow = R - 1 + r;
            Vg[idx] = (vrow >= 0 && vrow < IMG)
                ? __ldg(V + (size_t)(grp * 32 + ch) * HW + vrow * IMG + xc) : 0.f;
        }
        __syncthreads();
        for (int idx = tid; idx < 32 * 128; idx += 256) {
            int ch = idx >> 7, xc = idx & 127;
            const float* vr = Vg + ch * 384;
            const float* w9 = w9b + ch * 9;
            float a = bds[grp * 32 + ch];
#pragma unroll
            for (int dy = 0; dy < 3; dy++) {
                int base = dy * 128 + xc;
                if (xc > 0)   a += w9[dy * 3 + 0] * vr[base - 1];
                              a += w9[dy * 3 + 1] * vr[base];
                if (xc < 127) a += w9[dy * 3 + 2] * vr[base + 1];
            }
            cxs[(grp * 32 + ch) * 128 + xc] = a;
        }
    }
    __syncthreads();
    if (tid < 128) {
        float s = 0.f, s2 = 0.f;
        for (int c = 0; c < C; c++) { float v = cxs[c * 128 + tid]; s += v; s2 += v * v; }
        float mu = s * (1.f / C);
        float var = s2 * (1.f / C) - mu * mu;
        mus[tid] = mu; rss[tid] = rsqrtf(var + 1e-5f);
    }
    __syncthreads();

    if (EP == 0) {
        for (int idx = tid; idx < C * 128; idx += 256) {
            int c = idx >> 7, xc = idx & 127;
            float v = (cxs[idx] - mus[xc]) * rss[xc] * lnws[c] + lnbs[c];
            cxs[idx] = gelu_f(v);
        }
        __syncthreads();
        if (tid < 128) {
            float s = 0.f, mx = -1e30f;
            for (int c = 0; c < C; c++) { float v = cxs[c * 128 + tid]; s += v; mx = fmaxf(mx, v); }
            g_sm[R * 128 + tid]      = s * (1.f / C);
            g_sm[HW + R * 128 + tid] = mx;
        }
    } else {
        for (int idx = tid; idx < C * 128; idx += 256) {
            int c = idx >> 7, xc = idx & 127;
            float v = (cxs[idx] - mus[xc]) * rss[xc] * lnws[c] + lnbs[c];
            float gel = gelu_f(v);
            size_t gi = (size_t)c * HW + R * 128 + xc;
            S[gi] = S[gi] * g_sigsp[R * 128 + xc] + gel * g_sigcm[c];
        }
    }
}

// ============================================================================
// Slow-path conv branch (batch 7 only), 512 threads.
// ============================================================================
template<int EP>
__global__ void __launch_bounds__(512, 1) convx_k(
    const float* __restrict__ x, const float* __restrict__ wqkv,
    const float* __restrict__ wdw, const float* __restrict__ wdc,
    const float* __restrict__ bdc,
    const float* __restrict__ lnw, const float* __restrict__ lnb,
    float* __restrict__ S)
{
    extern __shared__ float sm[];
    float* cxs  = sm;               // 24576
    float* Wt   = cxs + 24576;      // 3072  : [c][16]
    float* Ys   = Wt + 3072;        // 10240 : 16ch x 640px
    float* Vs   = Ys + 10240;       // 6144  : 16ch x 384px
    float* w9a  = Vs + 6144;        // 144
    float* w9b  = w9a + 144;        // 144
    float* mus  = w9b + 144;        // 128
    float* rss  = mus + 128;        // 128
    float* lnws = rss + 128;        // 192
    float* lnbs = lnws + 192;       // 192
    float* bds  = lnbs + 192;       // 192

    const int tid = threadIdx.x;
    const int R = blockIdx.x;

    if (tid < C) { lnws[tid] = lnw[tid]; lnbs[tid] = lnb[tid]; bds[tid] = bdc[tid]; }

    for (int grp = 0; grp < 12; grp++) {
        const int cb16 = grp * 16;
        const int vcb  = 2 * C + cb16;
        __syncthreads();
        for (int i = tid; i < 3072; i += 512) {
            int c = i >> 4, j = i & 15;
            Wt[c * 16 + j] = wqkv[(size_t)(vcb + j) * C + c];
        }
        if (tid < 144) { w9a[tid] = wdw[vcb * 9 + tid]; w9b[tid] = wdc[cb16 * 9 + tid]; }
        __syncthreads();
        {
            int px = tid & 127, oh = tid >> 7;    // oh 0..3, 4 channels each
            for (int px0 = 0; px0 < 640; px0 += 128) {
                int p = px0 + px;
                int er = R - 2 + (p >> 7);
                int col = p & 127;
                float acc[4];
#pragma unroll
                for (int j = 0; j < 4; j++) acc[j] = 0.f;
                if (er >= 0 && er < IMG) {
                    const float* xp = x + er * IMG + col;
#pragma unroll 4
                    for (int c = 0; c < C; c++) {
                        float xv = __ldg(xp + (size_t)c * HW);
                        const float4* wr = (const float4*)(Wt + c * 16 + oh * 4);
                        float4 w0 = wr[0];
                        acc[0] += w0.x * xv; acc[1] += w0.y * xv;
                        acc[2] += w0.z * xv; acc[3] += w0.w * xv;
                    }
                }
#pragma unroll
                for (int j = 0; j < 4; j++) Ys[(oh * 4 + j) * 640 + p] = acc[j];
            }
        }
        __syncthreads();
        for (int idx = tid; idx < 16 * 384; idx += 512) {
            int j = idx / 384, p = idx % 384, r = p >> 7, xc = p & 127;
            int vrow = R - 1 + r;
            float a = 0.f;
            if (vrow >= 0 && vrow < IMG) {
                const float* yr = Ys + j * 640;
                const float* w9 = w9a + j * 9;
#pragma unroll
                for (int dy = 0; dy < 3; dy++) {
                    int base = (r + dy) * 128 + xc;
                    if (xc > 0)   a += w9[dy * 3 + 0] * yr[base - 1];
                                  a += w9[dy * 3 + 1] * yr[base];
                    if (xc < 127) a += w9[dy * 3 + 2] * yr[base + 1];
                }
            }
            Vs[j * 384 + r * 128 + xc] = a;
        }
        __syncthreads();
        for (int idx = tid; idx < 16 * 128; idx += 512) {
            int j = idx >> 7, xc = idx & 127;
            const float* vr = Vs + j * 384;
            const float* w9 = w9b + j * 9;
            float a = bds[cb16 + j];
#pragma unroll
            for (int dy = 0; dy < 3; dy++) {
                int base = dy * 128 + xc;
                if (xc > 0)   a += w9[dy * 3 + 0] * vr[base - 1];
                              a += w9[dy * 3 + 1] * vr[base];
                if (xc < 127) a += w9[dy * 3 + 2] * vr[base + 1];
            }
            cxs[(cb16 + j) * 128 + xc] = a;
        }
    }
    __syncthreads();
    if (tid < 128) {
        float s = 0.f, s2 = 0.f;
        for (int c = 0; c < C; c++) { float v = cxs[c * 128 + tid]; s += v; s2 += v * v; }
        float mu = s * (1.f / C);
        float var = s2 * (1.f / C) - mu * mu;
        mus[tid] = mu; rss[tid] = rsqrtf(var + 1e-5f);
    }
    __syncthreads();

    if (EP == 0) {
        for (int idx = tid; idx < C * 128; idx += 512) {
            int c = idx >> 7, xc = idx & 127;
            float v = (cxs[idx] - mus[xc]) * rss[xc] * lnws[c] + lnbs[c];
            cxs[idx] = gelu_f(v);
        }
        __syncthreads();
        if (tid < 128) {
            float s = 0.f, mx = -1e30f;
            for (int c = 0; c < C; c++) { float v = cxs[c * 128 + tid]; s += v; mx = fmaxf(mx, v); }
            g_sm[R * 128 + tid]      = s * (1.f / C);
            g_sm[HW + R * 128 + tid] = mx;
        }
    } else {
        for (int idx = tid; idx < C * 128; idx += 512) {
            int c = idx >> 7, xc = idx & 127;
            float v = (cxs[idx] - mus[xc]) * rss[xc] * lnws[c] + lnbs[c];
            float gel = gelu_f(v);
            size_t gi = (size_t)c * HW + R * 128 + xc;
            S[gi] = S[gi] * g_sigsp[R * 128 + xc] + gel * g_sigcm[c];
        }
    }
}

// ------------- in-place channel projection (512 threads) -------------------
__global__ void __launch_bounds__(512, 1) proj_k(
    const float* __restrict__ wproj, float* __restrict__ S)
{
    extern __shared__ float sm[];
    float* Ss  = sm;                 // 24576
    float* Wgt = Ss + 24576;         // 6144

    const int tid = threadIdx.x;
    const int chunk = blockIdx.x;
    for (int i = tid; i < C * 128; i += 512) {
        int c = i >> 7, l = i & 127;
        Ss[i] = S[(size_t)c * HW + chunk * 128 + l];
    }
    for (int og = 0; og < 6; og++) {
        __syncthreads();
        for (int i = tid; i < 6144; i += 512) {
            int c = i >> 5, j = i & 31;
            Wgt[c * 32 + j] = wproj[(size_t)(og * 32 + j) * C + c];
        }
        __syncthreads();
        int px = tid & 127, oh = tid >> 7;     // oh 0..3, 8 channels each
        float acc[8];
#pragma unroll
        for (int j = 0; j < 8; j++) acc[j] = 0.f;
#pragma unroll 4
        for (int c = 0; c < C; c++) {
            float sval = Ss[c * 128 + px];
            const float4* wr = (const float4*)(Wgt + c * 32 + oh * 8);
            float4 w0 = wr[0], w1 = wr[1];
            acc[0] += w0.x * sval; acc[1] += w0.y * sval;
            acc[2] += w0.z * sval; acc[3] += w0.w * sval;
            acc[4] += w1.x * sval; acc[5] += w1.y * sval;
            acc[6] += w1.z * sval; acc[7] += w1.w * sval;
        }
#pragma unroll
        for (int j = 0; j < 8; j++)
            S[(size_t)(og * 32 + oh * 8 + j) * HW + chunk * 128 + px] = acc[j];
    }
}

// ---------------- small kernels --------------------------------------------
__global__ void normfin_k()
{
    int tid = threadIdx.x;
    int g = tid >> 5, j = tid & 31;
    float qs = 0.f, ks = 0.f;
    for (int s = 0; s < STRIPS; s++) {
        qs += g_qsqp[(g * STRIPS + s) * 32 + j];
        ks += g_ksqp[(g * STRIPS + s) * 32 + j];
    }
    g_qn[tid] = fmaxf(sqrtf(qs), 1e-12f);
    g_kn[tid] = fmaxf(sqrtf(ks), 1e-12f);
}

__global__ void softmax_k()
{
    int h = blockIdx.x;
    int warp = threadIdx.x >> 5, lane = threadIdx.x & 31;
    for (int c = warp; c < 32; c += 8) {
        int d = lane;
        float v = 0.f;
        for (int s = 0; s < STRIPS; s++)
            v += g_gramp[(size_t)(h * STRIPS + s) * 1024 + c * 32 + d];
        v = v / (g_qn[h * CHD + c] * g_kn[h * CHD + d]) * 0.17677669529663687f;
        float m = v;
#pragma unroll
        for (int o = 16; o > 0; o >>= 1) m = fmaxf(m, __shfl_xor_sync(0xffffffffu, m, o));
        float e = expf(v - m);
        float sum = e;
#pragma unroll
        for (int o = 16; o > 0; o >>= 1) sum += __shfl_xor_sync(0xffffffffu, sum, o);
        g_attn[h * 1024 + d * 32 + c] = e / sum;   // transposed [d][c]
    }
}

__global__ void poolmlp_k(const float* __restrict__ w1, const float* __restrict__ b1,
                          const float* __restrict__ w2, const float* __restrict__ b2)
{
    __shared__ float pl[C], hid[24];
    int tid = threadIdx.x;
    {
        int g = tid >> 5, j = tid & 31;
        float s = 0.f;
        for (int st = 0; st < STRIPS; st++) s += g_outsump[(g * STRIPS + st) * 32 + j];
        pl[tid] = s * (1.f / HW);
    }
    __syncthreads();
    if (tid < 24) {
        float a = b1[tid];
        for (int c = 0; c < C; c++) a += w1[tid * C + c] * pl[c];
        hid[tid] = gelu_f(a);
    }
    __syncthreads();
    float a = b2[tid];
#pragma unroll
    for (int j = 0; j < 24; j++) a += w2[tid * 24 + j] * hid[j];
    g_sigcm[tid] = 1.f / (1.f + expf(-a));
}

__global__ void spatial_k(const float* __restrict__ wsi, const float* __restrict__ bsi)
{
    __shared__ float w[98];
    int tid = threadIdx.x;
    if (tid < 98) w[tid] = wsi[tid];
    __syncthreads();
    int pixel = blockIdx.x * 256 + tid;
    int y = pixel >> 7, xcol = pixel & 127;
    float acc = bsi[0];
#pragma unroll
    for (int cc = 0; cc < 2; cc++) {
        const float* sp = g_sm + (size_t)cc * HW;
        const float* wp = w + cc * 49;
        for (int ky = 0; ky < 7; ky++) {
            int yy = y + ky - 3;
            if (yy < 0 || yy >= IMG) continue;
            for (int kx = 0; kx < 7; kx++) {
                int xx = xcol + kx - 3;
                if (xx < 0 || xx >= IMG) continue;
                acc += wp[ky * 7 + kx] * sp[yy * IMG + xx];
            }
        }
    }
    g_sigsp[pixel] = 1.f / (1.f + expf(-acc));
}

// ---------------- launch ---------------------------------------------------
extern "C" void kernel_launch(void* const* d_in, const int* in_sizes, int n_in,
                              void* d_out, int out_size)
{
    (void)in_sizes; (void)n_in; (void)out_size;
    const float* x       = (const float*)d_in[0];
    const float* w_qkv   = (const float*)d_in[1];
    const float* w_dw    = (const float*)d_in[2];
    const float* w_dconv = (const float*)d_in[3];
    const float* b_dconv = (const float*)d_in[4];
    const float* ln_w    = (const float*)d_in[5];
    const float* ln_b    = (const float*)d_in[6];
    const float* w_ci1   = (const float*)d_in[7];
    const float* b_ci1   = (const float*)d_in[8];
    const float* w_ci2   = (const float*)d_in[9];
    const float* b_ci2   = (const float*)d_in[10];
    const float* w_si    = (const float*)d_in[11];
    const float* b_si    = (const float*)d_in[12];
    const float* w_proj  = (const float*)d_in[13];
    float* out = (float*)d_out;

    const size_t smF0 = (6144 + 24576 + 16384 + 288) * 4;
    const size_t smF1 = smF0 + 4096 * 4;
    const size_t smF2 = smF0 + 1536 * 4;
    const size_t smCX = (24576 + 3072 + 10240 + 6144 + 144 + 144 + 128 + 128 + 192 + 192 + 192) * 4;
    const size_t smCV = (24576 + 12288 + 288 + 128 + 128 + 192 + 192 + 192) * 4;
    const size_t smPJ = (24576 + 6144) * 4;
    cudaFuncSetAttribute(fused_k<0>, cudaFuncAttributeMaxDynamicSharedMemorySize, (int)smF0);
    cudaFuncSetAttribute(fused_k<1>, cudaFuncAttributeMaxDynamicSharedMemorySize, (int)smF1);
    cudaFuncSetAttribute(fused_k<2>, cudaFuncAttributeMaxDynamicSharedMemorySize, (int)smF2);
    cudaFuncSetAttribute(fused_k<3>, cudaFuncAttributeMaxDynamicSharedMemorySize, (int)smF0);
    cudaFuncSetAttribute(convx_k<0>, cudaFuncAttributeMaxDynamicSharedMemorySize, (int)smCX);
    cudaFuncSetAttribute(convx_k<1>, cudaFuncAttributeMaxDynamicSharedMemorySize, (int)smCX);
    cudaFuncSetAttribute(convV_k<0>, cudaFuncAttributeMaxDynamicSharedMemorySize, (int)smCV);
    cudaFuncSetAttribute(convV_k<1>, cudaFuncAttributeMaxDynamicSharedMemorySize, (int)smCV);
    cudaFuncSetAttribute(proj_k,     cudaFuncAttributeMaxDynamicSharedMemorySize, (int)smPJ);

    float* V = out + (size_t)7 * C * HW;   // slice 7: dead scratch for b<7

    for (int b = 0; b < BATCH; b++) {
        const float* xb = x + (size_t)b * C * HW;
        float* S = out + (size_t)b * C * HW;

        fused_k<0><<<dim3(STRIPS, NH), 512, smF0>>>(xb, w_qkv, w_dw, S);     // q -> S
        fused_k<1><<<dim3(STRIPS, NH), 512, smF1>>>(xb, w_qkv, w_dw, S);     // Gram
        normfin_k<<<1, C>>>();
        softmax_k<<<NH, 256>>>();

        if (b < 7) {
            fused_k<3><<<dim3(STRIPS, NH), 512, smF0>>>(xb, w_qkv, w_dw, V); // v -> V
            attnmix_k<<<dim3(STRIPS, NH), 512>>>(V, S);                      // out -> S
            poolmlp_k<<<1, C>>>(w_ci1, b_ci1, w_ci2, b_ci2);
            convV_k<0><<<IMG, 256, smCV>>>(V, w_dconv, b_dconv, ln_w, ln_b, S);  // maps
            spatial_k<<<HW / 256, 256>>>(w_si, b_si);
            convV_k<1><<<IMG, 256, smCV>>>(V, w_dconv, b_dconv, ln_w, ln_b, S);  // gate
        } else {
            fused_k<2><<<dim3(STRIPS, NH), 512, smF2>>>(xb, w_qkv, w_dw, S); // out -> S
            poolmlp_k<<<1, C>>>(w_ci1, b_ci1, w_ci2, b_ci2);
            convx_k<0><<<IMG, 512, smCX>>>(xb, w_qkv, w_dw, w_dconv, b_dconv, ln_w, ln_b, S);
            spatial_k<<<HW / 256, 256>>>(w_si, b_si);
            convx_k<1><<<IMG, 512, smCX>>>(xb, w_qkv, w_dw, w_dconv, b_dconv, ln_w, ln_b, S);
        }
        proj_k<<<IMG, 512, smPJ>>>(w_proj, S);                               // final
    }
}

// round 15
// speedup vs baseline: 1.1957x; 1.1957x over previous
#include <cuda_runtime.h>
#include <math.h>

#define BATCH 8
#define C     192
#define NH    6
#define CHD   32
#define HW    16384
#define IMG   128
#define T     4
#define STRIPS 32        // 128 / T

// ---------------- small device globals (~1.0 MiB total) ---------------------
__device__ float g_qsqp [NH * STRIPS * 32];
__device__ float g_ksqp [NH * STRIPS * 32];
__device__ float g_gramp[NH * STRIPS * 1024];
__device__ float g_qn[C];
__device__ float g_kn[C];
__device__ float g_attn[NH * 1024];               // softmaxed attn, [d*32+c]
__device__ float g_outsump[NH * STRIPS * 32];
__device__ float g_sigcm[C];
__device__ float g_sm[2 * HW];
__device__ float g_sigsp[HW];

__device__ __forceinline__ float gelu_f(float v) {
    return 0.5f * v * (1.f + erff(v * 0.70710678118654752f));
}

// ============================================================================
// Fused pass (256 threads): y = W_group(32ch)*x -> dw3x3(w_dw) -> epilogue.
// x is STAGED THROUGH SHARED MEMORY row-by-row (XZ region doubles as xs buffer
// during stage 1, then as zs + epilogue scratch afterwards).
// EP 0: q -> S + qsq | EP 1: k -> Gram + ksq | EP 2: out (slow) | EP 3: v -> S
// ============================================================================
template<int EP>
__global__ void __launch_bounds__(256, 1) fused_k(
    const float* __restrict__ x, const float* __restrict__ wqkv,
    const float* __restrict__ wdw, float* __restrict__ S)
{
    extern __shared__ float sm[];
    float* Wt  = sm;                 // 6144  : W group transposed [c][j]
    float* Ys  = Wt + 6144;          // 24576 : 32ch x 768px
    float* XZ  = Ys + 24576;         // 24576 : stage1 xs[192][128]; then
                                     //         zs[32][512] (16384) + scratch
    float* w9s = XZ + 24576;         // 288
    float* zs    = XZ;               // dwconv out (post stage-1)
    float* extra = XZ + 16384;       // EP1: qs[4096]; EP2: Ast[1024]+outws[256]

    const int tid = threadIdx.x;
    const int strip = blockIdx.x, g = blockIdx.y;
    const int qkvoff = (EP == 0) ? 0 : (EP == 1) ? C : 2 * C;
    const int cb = qkvoff + g * 32;
    const float* wb = wqkv + (size_t)cb * C;

    for (int i = tid; i < 6144; i += 256) {
        int c = i >> 5, j = i & 31;
        Wt[c * 32 + j] = wb[(size_t)j * C + c];
    }
    for (int i = tid; i < 288; i += 256) w9s[i] = wdw[cb * 9 + i];   // FIXED
    __syncthreads();

    const int R0 = strip * T;
    // ---- stage 1: GEMM y[32][768], one image row at a time through shared --
    {
        int px = tid & 127, oh = tid >> 7;     // oh in {0,1}, 16 ch each
        for (int px0 = 0; px0 < 6; px0++) {
            int er = R0 - 1 + px0;
            bool live = (er >= 0 && er < IMG);
            if (live) {
                // cooperative load xs[192][128] for row er (float4-coalesced)
                const float4* xsrc = (const float4*)(x + (size_t)er * IMG);
                float4* xdst = (float4*)XZ;
                for (int i = tid; i < 6144; i += 256) {
                    int c = i >> 5, l4 = i & 31;
                    xdst[c * 32 + l4] = xsrc[(size_t)c * (HW / 4) + l4];
                }
            }
            __syncthreads();
            float acc[16];
#pragma unroll
            for (int j = 0; j < 16; j++) acc[j] = 0.f;
            if (live) {
#pragma unroll 4
                for (int c = 0; c < C; c++) {
                    float xv = XZ[c * 128 + px];
                    const float4* wr = (const float4*)(Wt + c * 32 + oh * 16);
                    float4 w0 = wr[0], w1 = wr[1], w2 = wr[2], w3 = wr[3];
                    acc[0]  += w0.x * xv; acc[1]  += w0.y * xv;
                    acc[2]  += w0.z * xv; acc[3]  += w0.w * xv;
                    acc[4]  += w1.x * xv; acc[5]  += w1.y * xv;
                    acc[6]  += w1.z * xv; acc[7]  += w1.w * xv;
                    acc[8]  += w2.x * xv; acc[9]  += w2.y * xv;
                    acc[10] += w2.z * xv; acc[11] += w2.w * xv;
                    acc[12] += w3.x * xv; acc[13] += w3.y * xv;
                    acc[14] += w3.z * xv; acc[15] += w3.w * xv;
                }
            }
#pragma unroll
            for (int j = 0; j < 16; j++) Ys[(oh * 16 + j) * 768 + px0 * 128 + px] = acc[j];
            __syncthreads();   // XZ reused next iteration
        }
    }

    // ---- stage 2: dw3x3 (w_dw) -> zs[32][512] ----
    for (int idx = tid; idx < 32 * 512; idx += 256) {
        int j = idx >> 9, p = idx & 511, r = p >> 7, xc = p & 127;
        const float* yr = Ys + j * 768;
        const float* w9 = w9s + j * 9;
        float a = 0.f;
#pragma unroll
        for (int dy = 0; dy < 3; dy++) {
            int base = (r + dy) * 128 + xc;
            if (xc > 0)   a += w9[dy * 3 + 0] * yr[base - 1];
                          a += w9[dy * 3 + 1] * yr[base];
            if (xc < 127) a += w9[dy * 3 + 2] * yr[base + 1];
        }
        zs[idx] = a;
    }
    __syncthreads();

    const int w = tid >> 5, lane = tid & 31;   // 8 warps

    if (EP == 0 || EP == 3) {
        for (int idx = tid; idx < 32 * 512; idx += 256) {
            int j = idx >> 9, p = idx & 511;
            S[(size_t)(g * 32 + j) * HW + strip * 512 + p] = zs[idx];
        }
    }
    if (EP == 0) {
#pragma unroll
        for (int m = 0; m < 4; m++) {
            int j = w * 4 + m;
            float s = 0.f;
            for (int t = 0; t < 16; t++) { float v = zs[j * 512 + lane + 32 * t]; s += v * v; }
#pragma unroll
            for (int off = 16; off > 0; off >>= 1) s += __shfl_down_sync(0xffffffffu, s, off);
            if (lane == 0) g_qsqp[(g * STRIPS + strip) * 32 + j] = s;
        }
    }

    if (EP == 1) {
        float* qs = extra;                       // 32 x 128 chunk of q
        int a_ = tid >> 4, b_ = tid & 15;
        float ga00 = 0.f, ga01 = 0.f, ga10 = 0.f, ga11 = 0.f;
        for (int ch = 0; ch < 4; ch++) {
            __syncthreads();
            for (int i = tid; i < 4096; i += 256) {
                int j = i >> 7, l = i & 127;
                qs[j * 128 + l] = S[(size_t)(g * 32 + j) * HW + strip * 512 + ch * 128 + l];
            }
            __syncthreads();
            const float* k0p = zs + (2 * b_) * 512 + ch * 128;
            const float* k1p = zs + (2 * b_ + 1) * 512 + ch * 128;
            const float* q0p = qs + (2 * a_) * 128;
            const float* q1p = qs + (2 * a_ + 1) * 128;
#pragma unroll 4
            for (int l = 0; l < 128; l++) {
                float q0 = q0p[l], q1 = q1p[l], k0 = k0p[l], k1 = k1p[l];
                ga00 += q0 * k0; ga01 += q0 * k1; ga10 += q1 * k0; ga11 += q1 * k1;
            }
        }
        float* gp = g_gramp + (size_t)(g * STRIPS + strip) * 1024;
        gp[(2 * a_) * 32 + 2 * b_]     = ga00;
        gp[(2 * a_) * 32 + 2 * b_ + 1] = ga01;
        gp[(2 * a_ + 1) * 32 + 2 * b_]     = ga10;
        gp[(2 * a_ + 1) * 32 + 2 * b_ + 1] = ga11;
#pragma unroll
        for (int m = 0; m < 4; m++) {
            int j = w * 4 + m;
            float s = 0.f;
            for (int t = 0; t < 16; t++) { float v = zs[j * 512 + lane + 32 * t]; s += v * v; }
#pragma unroll
            for (int off = 16; off > 0; off >>= 1) s += __shfl_down_sync(0xffffffffu, s, off);
            if (lane == 0) g_ksqp[(g * STRIPS + strip) * 32 + j] = s;
        }
    }

    if (EP == 2) {
        float* Ast = extra;                      // [d][c]
        float* outws = extra + 1024;             // 256
        for (int i = tid; i < 1024; i += 256) Ast[i] = g_attn[g * 1024 + i];
        __syncthreads();
        float osum[32];
#pragma unroll
        for (int c = 0; c < 32; c++) osum[c] = 0.f;
        for (int ph = 0; ph < 2; ph++) {
            int p = ph * 256 + tid;
            float acc[32];
#pragma unroll
            for (int c = 0; c < 32; c++) acc[c] = 0.f;
#pragma unroll 2
            for (int d = 0; d < 32; d++) {
                float vv = zs[d * 512 + p];
                const float4* ar = (const float4*)(Ast + d * 32);
#pragma unroll
                for (int q = 0; q < 8; q++) {
                    float4 a4 = ar[q];
                    acc[4 * q + 0] += a4.x * vv; acc[4 * q + 1] += a4.y * vv;
                    acc[4 * q + 2] += a4.z * vv; acc[4 * q + 3] += a4.w * vv;
                }
            }
#pragma unroll
            for (int c = 0; c < 32; c++) {
                S[(size_t)(g * 32 + c) * HW + strip * 512 + p] = acc[c];
                float v = acc[c];
#pragma unroll
                for (int off = 16; off > 0; off >>= 1) v += __shfl_down_sync(0xffffffffu, v, off);
                if (lane == 0) osum[c] += v;
            }
        }
        if (lane == 0)
            for (int c = 0; c < 32; c++) outws[w * 32 + c] = osum[c];
        __syncthreads();
        if (tid < 32) {
            float s = 0.f;
            for (int w2 = 0; w2 < 8; w2++) s += outws[w2 * 32 + tid];
            g_outsump[(g * STRIPS + strip) * 32 + tid] = s;
        }
    }
}

// ============================================================================
// Fast-path attention mix (256 threads): S = A · V per head + pooled partials.
// ============================================================================
__global__ void __launch_bounds__(256, 1) attnmix_k(
    const float* __restrict__ V, float* __restrict__ S)
{
    __shared__ float Ast[1024];
    __shared__ float outws[256];
    const int strip = blockIdx.x, h = blockIdx.y;
    const int tid = threadIdx.x;
    for (int i = tid; i < 1024; i += 256) Ast[i] = g_attn[h * 1024 + i];
    __syncthreads();
    const int w = tid >> 5, lane = tid & 31;
    float osum[32];
#pragma unroll
    for (int c = 0; c < 32; c++) osum[c] = 0.f;
    for (int ph = 0; ph < 2; ph++) {
        int p = strip * 512 + ph * 256 + tid;
        float acc[32];
#pragma unroll
        for (int c = 0; c < 32; c++) acc[c] = 0.f;
#pragma unroll 4
        for (int d = 0; d < 32; d++) {
            float vv = __ldg(V + (size_t)(h * 32 + d) * HW + p);
            const float4* ar = (const float4*)(Ast + d * 32);
#pragma unroll
            for (int q = 0; q < 8; q++) {
                float4 a4 = ar[q];
                acc[4 * q + 0] += a4.x * vv; acc[4 * q + 1] += a4.y * vv;
                acc[4 * q + 2] += a4.z * vv; acc[4 * q + 3] += a4.w * vv;
            }
        }
#pragma unroll
        for (int c = 0; c < 32; c++) {
            S[(size_t)(h * 32 + c) * HW + p] = acc[c];
            float v = acc[c];
#pragma unroll
            for (int off = 16; off > 0; off >>= 1) v += __shfl_down_sync(0xffffffffu, v, off);
            if (lane == 0) osum[c] += v;
        }
    }
    if (lane == 0)
        for (int c = 0; c < 32; c++) outws[w * 32 + c] = osum[c];
    __syncthreads();
    if (tid < 32) {
        float s = 0.f;
        for (int w2 = 0; w2 < 8; w2++) s += outws[w2 * 32 + tid];
        g_outsump[(h * STRIPS + strip) * 32 + tid] = s;
    }
}

// ============================================================================
// Fast-path conv branch from stored V (256 threads).
// ============================================================================
template<int EP>
__global__ void __launch_bounds__(256, 1) convV_k(
    const float* __restrict__ V, const float* __restrict__ wdc,
    const float* __restrict__ bdc, const float* __restrict__ lnw,
    const float* __restrict__ lnb, float* __restrict__ S)
{
    extern __shared__ float sm[];
    float* cxs  = sm;               // 24576
    float* Vg   = cxs + 24576;      // 12288 : 32ch x 384px
    float* w9b  = Vg + 12288;       // 288
    float* mus  = w9b + 288;        // 128
    float* rss  = mus + 128;        // 128
    float* lnws = rss + 128;        // 192
    float* lnbs = lnws + 192;       // 192
    float* bds  = lnbs + 192;       // 192

    const int tid = threadIdx.x;
    const int R = blockIdx.x;
    if (tid < C) { lnws[tid] = lnw[tid]; lnbs[tid] = lnb[tid]; bds[tid] = bdc[tid]; }

    for (int grp = 0; grp < 6; grp++) {
        __syncthreads();
        for (int i = tid; i < 288; i += 256) w9b[i] = wdc[(grp * 32) * 9 + i];
        for (int idx = tid; idx < 32 * 384; idx += 256) {
            int ch = idx / 384, p = idx % 384, r = p >> 7, xc = p & 127;
            int vrow = R - 1 + r;
            Vg[idx] = (vrow >= 0 && vrow < IMG)
                ? __ldg(V + (size_t)(grp * 32 + ch) * HW + vrow * IMG + xc) : 0.f;
        }
        __syncthreads();
        for (int idx = tid; idx < 32 * 128; idx += 256) {
            int ch = idx >> 7, xc = idx & 127;
            const float* vr = Vg + ch * 384;
            const float* w9 = w9b + ch * 9;
            float a = bds[grp * 32 + ch];
#pragma unroll
            for (int dy = 0; dy < 3; dy++) {
                int base = dy * 128 + xc;
                if (xc > 0)   a += w9[dy * 3 + 0] * vr[base - 1];
                              a += w9[dy * 3 + 1] * vr[base];
                if (xc < 127) a += w9[dy * 3 + 2] * vr[base + 1];
            }
            cxs[(grp * 32 + ch) * 128 + xc] = a;
        }
    }
    __syncthreads();
    if (tid < 128) {
        float s = 0.f, s2 = 0.f;
        for (int c = 0; c < C; c++) { float v = cxs[c * 128 + tid]; s += v; s2 += v * v; }
        float mu = s * (1.f / C);
        float var = s2 * (1.f / C) - mu * mu;
        mus[tid] = mu; rss[tid] = rsqrtf(var + 1e-5f);
    }
    __syncthreads();

    if (EP == 0) {
        for (int idx = tid; idx < C * 128; idx += 256) {
            int c = idx >> 7, xc = idx & 127;
            float v = (cxs[idx] - mus[xc]) * rss[xc] * lnws[c] + lnbs[c];
            cxs[idx] = gelu_f(v);
        }
        __syncthreads();
        if (tid < 128) {
            float s = 0.f, mx = -1e30f;
            for (int c = 0; c < C; c++) { float v = cxs[c * 128 + tid]; s += v; mx = fmaxf(mx, v); }
            g_sm[R * 128 + tid]      = s * (1.f / C);
            g_sm[HW + R * 128 + tid] = mx;
        }
    } else {
        for (int idx = tid; idx < C * 128; idx += 256) {
            int c = idx >> 7, xc = idx & 127;
            float v = (cxs[idx] - mus[xc]) * rss[xc] * lnws[c] + lnbs[c];
            float gel = gelu_f(v);
            size_t gi = (size_t)c * HW + R * 128 + xc;
            S[gi] = S[gi] * g_sigsp[R * 128 + xc] + gel * g_sigcm[c];
        }
    }
}

// ============================================================================
// Slow-path conv branch (batch 7 only), 256 threads (R12-proven).
// ============================================================================
template<int EP>
__global__ void __launch_bounds__(256, 1) convx_k(
    const float* __restrict__ x, const float* __restrict__ wqkv,
    const float* __restrict__ wdw, const float* __restrict__ wdc,
    const float* __restrict__ bdc,
    const float* __restrict__ lnw, const float* __restrict__ lnb,
    float* __restrict__ S)
{
    extern __shared__ float sm[];
    float* cxs  = sm;               // 24576
    float* Wt   = cxs + 24576;      // 3072  : [c][16]
    float* Ys   = Wt + 3072;        // 10240 : 16ch x 640px
    float* Vs   = Ys + 10240;       // 6144  : 16ch x 384px
    float* w9a  = Vs + 6144;        // 144
    float* w9b  = w9a + 144;        // 144
    float* mus  = w9b + 144;        // 128
    float* rss  = mus + 128;        // 128
    float* lnws = rss + 128;        // 192
    float* lnbs = lnws + 192;       // 192
    float* bds  = lnbs + 192;       // 192

    const int tid = threadIdx.x;
    const int R = blockIdx.x;

    if (tid < C) { lnws[tid] = lnw[tid]; lnbs[tid] = lnb[tid]; bds[tid] = bdc[tid]; }

    for (int grp = 0; grp < 12; grp++) {
        const int cb16 = grp * 16;
        const int vcb  = 2 * C + cb16;
        __syncthreads();
        for (int i = tid; i < 3072; i += 256) {
            int c = i >> 4, j = i & 15;
            Wt[c * 16 + j] = wqkv[(size_t)(vcb + j) * C + c];
        }
        if (tid < 144) { w9a[tid] = wdw[vcb * 9 + tid]; w9b[tid] = wdc[cb16 * 9 + tid]; }
        __syncthreads();
        {
            int px = tid & 127, oh = tid >> 7;
            for (int px0 = 0; px0 < 640; px0 += 128) {
                int p = px0 + px;
                int er = R - 2 + (p >> 7);
                int col = p & 127;
                float acc[8];
#pragma unroll
                for (int j = 0; j < 8; j++) acc[j] = 0.f;
                if (er >= 0 && er < IMG) {
                    const float* xp = x + er * IMG + col;
#pragma unroll 4
                    for (int c = 0; c < C; c++) {
                        float xv = __ldg(xp + (size_t)c * HW);
                        const float4* wr = (const float4*)(Wt + c * 16 + oh * 8);
                        float4 w0 = wr[0], w1 = wr[1];
                        acc[0] += w0.x * xv; acc[1] += w0.y * xv;
                        acc[2] += w0.z * xv; acc[3] += w0.w * xv;
                        acc[4] += w1.x * xv; acc[5] += w1.y * xv;
                        acc[6] += w1.z * xv; acc[7] += w1.w * xv;
                    }
                }
#pragma unroll
                for (int j = 0; j < 8; j++) Ys[(oh * 8 + j) * 640 + p] = acc[j];
            }
        }
        __syncthreads();
        for (int idx = tid; idx < 16 * 384; idx += 256) {
            int j = idx / 384, p = idx % 384, r = p >> 7, xc = p & 127;
            int vrow = R - 1 + r;
            float a = 0.f;
            if (vrow >= 0 && vrow < IMG) {
                const float* yr = Ys + j * 640;
                const float* w9 = w9a + j * 9;
#pragma unroll
                for (int dy = 0; dy < 3; dy++) {
                    int base = (r + dy) * 128 + xc;
                    if (xc > 0)   a += w9[dy * 3 + 0] * yr[base - 1];
                                  a += w9[dy * 3 + 1] * yr[base];
                    if (xc < 127) a += w9[dy * 3 + 2] * yr[base + 1];
                }
            }
            Vs[j * 384 + r * 128 + xc] = a;
        }
        __syncthreads();
        for (int idx = tid; idx < 16 * 128; idx += 256) {
            int j = idx >> 7, xc = idx & 127;
            const float* vr = Vs + j * 384;
            const float* w9 = w9b + j * 9;
            float a = bds[cb16 + j];
#pragma unroll
            for (int dy = 0; dy < 3; dy++) {
                int base = dy * 128 + xc;
                if (xc > 0)   a += w9[dy * 3 + 0] * vr[base - 1];
                              a += w9[dy * 3 + 1] * vr[base];
                if (xc < 127) a += w9[dy * 3 + 2] * vr[base + 1];
            }
            cxs[(cb16 + j) * 128 + xc] = a;
        }
    }
    __syncthreads();
    if (tid < 128) {
        float s = 0.f, s2 = 0.f;
        for (int c = 0; c < C; c++) { float v = cxs[c * 128 + tid]; s += v; s2 += v * v; }
        float mu = s * (1.f / C);
        float var = s2 * (1.f / C) - mu * mu;
        mus[tid] = mu; rss[tid] = rsqrtf(var + 1e-5f);
    }
    __syncthreads();

    if (EP == 0) {
        for (int idx = tid; idx < C * 128; idx += 256) {
            int c = idx >> 7, xc = idx & 127;
            float v = (cxs[idx] - mus[xc]) * rss[xc] * lnws[c] + lnbs[c];
            cxs[idx] = gelu_f(v);
        }
        __syncthreads();
        if (tid < 128) {
            float s = 0.f, mx = -1e30f;
            for (int c = 0; c < C; c++) { float v = cxs[c * 128 + tid]; s += v; mx = fmaxf(mx, v); }
            g_sm[R * 128 + tid]      = s * (1.f / C);
            g_sm[HW + R * 128 + tid] = mx;
        }
    } else {
        for (int idx = tid; idx < C * 128; idx += 256) {
            int c = idx >> 7, xc = idx & 127;
            float v = (cxs[idx] - mus[xc]) * rss[xc] * lnws[c] + lnbs[c];
            float gel = gelu_f(v);
            size_t gi = (size_t)c * HW + R * 128 + xc;
            S[gi] = S[gi] * g_sigsp[R * 128 + xc] + gel * g_sigcm[c];
        }
    }
}

// ------------- in-place channel projection (256 threads, R12) --------------
__global__ void __launch_bounds__(256, 1) proj_k(
    const float* __restrict__ wproj, float* __restrict__ S)
{
    extern __shared__ float sm[];
    float* Ss  = sm;                 // 24576
    float* Wgt = Ss + 24576;         // 6144

    const int tid = threadIdx.x;
    const int chunk = blockIdx.x;
    for (int i = tid; i < C * 128; i += 256) {
        int c = i >> 7, l = i & 127;
        Ss[i] = S[(size_t)c * HW + chunk * 128 + l];
    }
    for (int og = 0; og < 6; og++) {
        __syncthreads();
        for (int i = tid; i < 6144; i += 256) {
            int c = i >> 5, j = i & 31;
            Wgt[c * 32 + j] = wproj[(size_t)(og * 32 + j) * C + c];
        }
        __syncthreads();
        int px = tid & 127, oh = tid >> 7;
        float acc[16];
#pragma unroll
        for (int j = 0; j < 16; j++) acc[j] = 0.f;
#pragma unroll 4
        for (int c = 0; c < C; c++) {
            float sval = Ss[c * 128 + px];
            const float4* wr = (const float4*)(Wgt + c * 32 + oh * 16);
            float4 w0 = wr[0], w1 = wr[1], w2 = wr[2], w3 = wr[3];
            acc[0]  += w0.x * sval; acc[1]  += w0.y * sval;
            acc[2]  += w0.z * sval; acc[3]  += w0.w * sval;
            acc[4]  += w1.x * sval; acc[5]  += w1.y * sval;
            acc[6]  += w1.z * sval; acc[7]  += w1.w * sval;
            acc[8]  += w2.x * sval; acc[9]  += w2.y * sval;
            acc[10] += w2.z * sval; acc[11] += w2.w * sval;
            acc[12] += w3.x * sval; acc[13] += w3.y * sval;
            acc[14] += w3.z * sval; acc[15] += w3.w * sval;
        }
#pragma unroll
        for (int j = 0; j < 16; j++)
            S[(size_t)(og * 32 + oh * 16 + j) * HW + chunk * 128 + px] = acc[j];
    }
}

// ---------------- small kernels --------------------------------------------
__global__ void normfin_k()
{
    int tid = threadIdx.x;
    int g = tid >> 5, j = tid & 31;
    float qs = 0.f, ks = 0.f;
    for (int s = 0; s < STRIPS; s++) {
        qs += g_qsqp[(g * STRIPS + s) * 32 + j];
        ks += g_ksqp[(g * STRIPS + s) * 32 + j];
    }
    g_qn[tid] = fmaxf(sqrtf(qs), 1e-12f);
    g_kn[tid] = fmaxf(sqrtf(ks), 1e-12f);
}

__global__ void softmax_k()
{
    int h = blockIdx.x;
    int warp = threadIdx.x >> 5, lane = threadIdx.x & 31;
    for (int c = warp; c < 32; c += 8) {
        int d = lane;
        float v = 0.f;
        for (int s = 0; s < STRIPS; s++)
            v += g_gramp[(size_t)(h * STRIPS + s) * 1024 + c * 32 + d];
        v = v / (g_qn[h * CHD + c] * g_kn[h * CHD + d]) * 0.17677669529663687f;
        float m = v;
#pragma unroll
        for (int o = 16; o > 0; o >>= 1) m = fmaxf(m, __shfl_xor_sync(0xffffffffu, m, o));
        float e = expf(v - m);
        float sum = e;
#pragma unroll
        for (int o = 16; o > 0; o >>= 1) sum += __shfl_xor_sync(0xffffffffu, sum, o);
        g_attn[h * 1024 + d * 32 + c] = e / sum;   // transposed [d][c]
    }
}

__global__ void poolmlp_k(const float* __restrict__ w1, const float* __restrict__ b1,
                          const float* __restrict__ w2, const float* __restrict__ b2)
{
    __shared__ float pl[C], hid[24];
    int tid = threadIdx.x;
    {
        int g = tid >> 5, j = tid & 31;
        float s = 0.f;
        for (int st = 0; st < STRIPS; st++) s += g_outsump[(g * STRIPS + st) * 32 + j];
        pl[tid] = s * (1.f / HW);
    }
    __syncthreads();
    if (tid < 24) {
        float a = b1[tid];
        for (int c = 0; c < C; c++) a += w1[tid * C + c] * pl[c];
        hid[tid] = gelu_f(a);
    }
    __syncthreads();
    float a = b2[tid];
#pragma unroll
    for (int j = 0; j < 24; j++) a += w2[tid * 24 + j] * hid[j];
    g_sigcm[tid] = 1.f / (1.f + expf(-a));
}

__global__ void spatial_k(const float* __restrict__ wsi, const float* __restrict__ bsi)
{
    __shared__ float w[98];
    int tid = threadIdx.x;
    if (tid < 98) w[tid] = wsi[tid];
    __syncthreads();
    int pixel = blockIdx.x * 256 + tid;
    int y = pixel >> 7, xcol = pixel & 127;
    float acc = bsi[0];
#pragma unroll
    for (int cc = 0; cc < 2; cc++) {
        const float* sp = g_sm + (size_t)cc * HW;
        const float* wp = w + cc * 49;
        for (int ky = 0; ky < 7; ky++) {
            int yy = y + ky - 3;
            if (yy < 0 || yy >= IMG) continue;
            for (int kx = 0; kx < 7; kx++) {
                int xx = xcol + kx - 3;
                if (xx < 0 || xx >= IMG) continue;
                acc += wp[ky * 7 + kx] * sp[yy * IMG + xx];
            }
        }
    }
    g_sigsp[pixel] = 1.f / (1.f + expf(-acc));
}

// ---------------- launch ---------------------------------------------------
extern "C" void kernel_launch(void* const* d_in, const int* in_sizes, int n_in,
                              void* d_out, int out_size)
{
    (void)in_sizes; (void)n_in; (void)out_size;
    const float* x       = (const float*)d_in[0];
    const float* w_qkv   = (const float*)d_in[1];
    const float* w_dw    = (const float*)d_in[2];
    const float* w_dconv = (const float*)d_in[3];
    const float* b_dconv = (const float*)d_in[4];
    const float* ln_w    = (const float*)d_in[5];
    const float* ln_b    = (const float*)d_in[6];
    const float* w_ci1   = (const float*)d_in[7];
    const float* b_ci1   = (const float*)d_in[8];
    const float* w_ci2   = (const float*)d_in[9];
    const float* b_ci2   = (const float*)d_in[10];
    const float* w_si    = (const float*)d_in[11];
    const float* b_si    = (const float*)d_in[12];
    const float* w_proj  = (const float*)d_in[13];
    float* out = (float*)d_out;

    const size_t smF  = (6144 + 24576 + 24576 + 288) * 4;   // 222336 B
    const size_t smCX = (24576 + 3072 + 10240 + 6144 + 144 + 144 + 128 + 128 + 192 + 192 + 192) * 4;
    const size_t smCV = (24576 + 12288 + 288 + 128 + 128 + 192 + 192 + 192) * 4;
    const size_t smPJ = (24576 + 6144) * 4;
    cudaFuncSetAttribute(fused_k<0>, cudaFuncAttributeMaxDynamicSharedMemorySize, (int)smF);
    cudaFuncSetAttribute(fused_k<1>, cudaFuncAttributeMaxDynamicSharedMemorySize, (int)smF);
    cudaFuncSetAttribute(fused_k<2>, cudaFuncAttributeMaxDynamicSharedMemorySize, (int)smF);
    cudaFuncSetAttribute(fused_k<3>, cudaFuncAttributeMaxDynamicSharedMemorySize, (int)smF);
    cudaFuncSetAttribute(convx_k<0>, cudaFuncAttributeMaxDynamicSharedMemorySize, (int)smCX);
    cudaFuncSetAttribute(convx_k<1>, cudaFuncAttributeMaxDynamicSharedMemorySize, (int)smCX);
    cudaFuncSetAttribute(convV_k<0>, cudaFuncAttributeMaxDynamicSharedMemorySize, (int)smCV);
    cudaFuncSetAttribute(convV_k<1>, cudaFuncAttributeMaxDynamicSharedMemorySize, (int)smCV);
    cudaFuncSetAttribute(proj_k,     cudaFuncAttributeMaxDynamicSharedMemorySize, (int)smPJ);

    float* V = out + (size_t)7 * C * HW;   // slice 7: dead scratch for b<7

    for (int b = 0; b < BATCH; b++) {
        const float* xb = x + (size_t)b * C * HW;
        float* S = out + (size_t)b * C * HW;

        fused_k<0><<<dim3(STRIPS, NH), 256, smF>>>(xb, w_qkv, w_dw, S);      // q -> S
        fused_k<1><<<dim3(STRIPS, NH), 256, smF>>>(xb, w_qkv, w_dw, S);      // Gram
        normfin_k<<<1, C>>>();
        softmax_k<<<NH, 256>>>();

        if (b < 7) {
            fused_k<3><<<dim3(STRIPS, NH), 256, smF>>>(xb, w_qkv, w_dw, V);  // v -> V
            attnmix_k<<<dim3(STRIPS, NH), 256>>>(V, S);                      // out -> S
            poolmlp_k<<<1, C>>>(w_ci1, b_ci1, w_ci2, b_ci2);
            convV_k<0><<<IMG, 256, smCV>>>(V, w_dconv, b_dconv, ln_w, ln_b, S);  // maps
            spatial_k<<<HW / 256, 256>>>(w_si, b_si);
            convV_k<1><<<IMG, 256, smCV>>>(V, w_dconv, b_dconv, ln_w, ln_b, S);  // gate
        } else {
            fused_k<2><<<dim3(STRIPS, NH), 256, smF>>>(xb, w_qkv, w_dw, S);  // out -> S
            poolmlp_k<<<1, C>>>(w_ci1, b_ci1, w_ci2, b_ci2);
            convx_k<0><<<IMG, 256, smCX>>>(xb, w_qkv, w_dw, w_dconv, b_dconv, ln_w, ln_b, S);
            spatial_k<<<HW / 256, 256>>>(w_si, b_si);
            convx_k<1><<<IMG, 256, smCX>>>(xb, w_qkv, w_dw, w_dconv, b_dconv, ln_w, ln_b, S);
        }
        proj_k<<<IMG, 256, smPJ>>>(w_proj, S);                               // final
    }
}

// round 16
// speedup vs baseline: 1.4573x; 1.2188x over previous
#include <cuda_runtime.h>
#include <math.h>

#define BATCH 8
#define C     192
#define NH    6
#define CHD   32
#define HW    16384
#define IMG   128
#define T     4
#define STRIPS 32        // 128 / T

// ---------------- device globals (~13 MiB total) -----------------------------
__device__ float g_V[(size_t)C * HW];             // 12 MiB: v for current batch
__device__ float g_qsqp [NH * STRIPS * 32];
__device__ float g_ksqp [NH * STRIPS * 32];
__device__ float g_gramp[NH * STRIPS * 1024];
__device__ float g_qn[C];
__device__ float g_kn[C];
__device__ float g_attn[NH * 1024];               // softmaxed attn, [d*32+c]
__device__ float g_outsump[NH * STRIPS * 32];
__device__ float g_sigcm[C];
__device__ float g_sm[2 * HW];
__device__ float g_sigsp[HW];

__device__ __forceinline__ float gelu_f(float v) {
    return 0.5f * v * (1.f + erff(v * 0.70710678118654752f));
}

// ============================================================================
// Fused pass (256 threads): y = W_group(32ch)*x -> dw3x3(w_dw) -> epilogue.
// x staged through shared memory row-by-row (XZ doubles as xs then zs).
// EP 0: q -> S + qsq | EP 1: k -> Gram + ksq | EP 3: v -> S
// ============================================================================
template<int EP>
__global__ void __launch_bounds__(256, 1) fused_k(
    const float* __restrict__ x, const float* __restrict__ wqkv,
    const float* __restrict__ wdw, float* __restrict__ S)
{
    extern __shared__ float sm[];
    float* Wt  = sm;                 // 6144  : W group transposed [c][j]
    float* Ys  = Wt + 6144;          // 24576 : 32ch x 768px
    float* XZ  = Ys + 24576;         // 24576 : stage1 xs[192][128]; then zs
    float* w9s = XZ + 24576;         // 288
    float* zs    = XZ;               // dwconv out (post stage-1)
    float* extra = XZ + 16384;       // EP1: qs[4096]

    const int tid = threadIdx.x;
    const int strip = blockIdx.x, g = blockIdx.y;
    const int qkvoff = (EP == 0) ? 0 : (EP == 1) ? C : 2 * C;
    const int cb = qkvoff + g * 32;
    const float* wb = wqkv + (size_t)cb * C;

    for (int i = tid; i < 6144; i += 256) {
        int c = i >> 5, j = i & 31;
        Wt[c * 32 + j] = wb[(size_t)j * C + c];
    }
    for (int i = tid; i < 288; i += 256) w9s[i] = wdw[cb * 9 + i];
    __syncthreads();

    const int R0 = strip * T;
    // ---- stage 1: GEMM y[32][768], one image row at a time through shared --
    {
        int px = tid & 127, oh = tid >> 7;     // oh in {0,1}, 16 ch each
        for (int px0 = 0; px0 < 6; px0++) {
            int er = R0 - 1 + px0;
            bool live = (er >= 0 && er < IMG);
            if (live) {
                const float4* xsrc = (const float4*)(x + (size_t)er * IMG);
                float4* xdst = (float4*)XZ;
                for (int i = tid; i < 6144; i += 256) {
                    int c = i >> 5, l4 = i & 31;
                    xdst[c * 32 + l4] = xsrc[(size_t)c * (HW / 4) + l4];
                }
            }
            __syncthreads();
            float acc[16];
#pragma unroll
            for (int j = 0; j < 16; j++) acc[j] = 0.f;
            if (live) {
#pragma unroll 4
                for (int c = 0; c < C; c++) {
                    float xv = XZ[c * 128 + px];
                    const float4* wr = (const float4*)(Wt + c * 32 + oh * 16);
                    float4 w0 = wr[0], w1 = wr[1], w2 = wr[2], w3 = wr[3];
                    acc[0]  += w0.x * xv; acc[1]  += w0.y * xv;
                    acc[2]  += w0.z * xv; acc[3]  += w0.w * xv;
                    acc[4]  += w1.x * xv; acc[5]  += w1.y * xv;
                    acc[6]  += w1.z * xv; acc[7]  += w1.w * xv;
                    acc[8]  += w2.x * xv; acc[9]  += w2.y * xv;
                    acc[10] += w2.z * xv; acc[11] += w2.w * xv;
                    acc[12] += w3.x * xv; acc[13] += w3.y * xv;
                    acc[14] += w3.z * xv; acc[15] += w3.w * xv;
                }
            }
#pragma unroll
            for (int j = 0; j < 16; j++) Ys[(oh * 16 + j) * 768 + px0 * 128 + px] = acc[j];
            __syncthreads();
        }
    }

    // ---- stage 2: dw3x3 (w_dw) -> zs[32][512] ----
    for (int idx = tid; idx < 32 * 512; idx += 256) {
        int j = idx >> 9, p = idx & 511, r = p >> 7, xc = p & 127;
        const float* yr = Ys + j * 768;
        const float* w9 = w9s + j * 9;
        float a = 0.f;
#pragma unroll
        for (int dy = 0; dy < 3; dy++) {
            int base = (r + dy) * 128 + xc;
            if (xc > 0)   a += w9[dy * 3 + 0] * yr[base - 1];
                          a += w9[dy * 3 + 1] * yr[base];
            if (xc < 127) a += w9[dy * 3 + 2] * yr[base + 1];
        }
        zs[idx] = a;
    }
    __syncthreads();

    const int w = tid >> 5, lane = tid & 31;   // 8 warps

    if (EP == 0 || EP == 3) {
        for (int idx = tid; idx < 32 * 512; idx += 256) {
            int j = idx >> 9, p = idx & 511;
            S[(size_t)(g * 32 + j) * HW + strip * 512 + p] = zs[idx];
        }
    }
    if (EP == 0) {
#pragma unroll
        for (int m = 0; m < 4; m++) {
            int j = w * 4 + m;
            float s = 0.f;
            for (int t = 0; t < 16; t++) { float v = zs[j * 512 + lane + 32 * t]; s += v * v; }
#pragma unroll
            for (int off = 16; off > 0; off >>= 1) s += __shfl_down_sync(0xffffffffu, s, off);
            if (lane == 0) g_qsqp[(g * STRIPS + strip) * 32 + j] = s;
        }
    }

    if (EP == 1) {
        float* qs = extra;                       // 32 x 128 chunk of q
        int a_ = tid >> 4, b_ = tid & 15;
        float ga00 = 0.f, ga01 = 0.f, ga10 = 0.f, ga11 = 0.f;
        for (int ch = 0; ch < 4; ch++) {
            __syncthreads();
            for (int i = tid; i < 4096; i += 256) {
                int j = i >> 7, l = i & 127;
                qs[j * 128 + l] = S[(size_t)(g * 32 + j) * HW + strip * 512 + ch * 128 + l];
            }
            __syncthreads();
            const float* k0p = zs + (2 * b_) * 512 + ch * 128;
            const float* k1p = zs + (2 * b_ + 1) * 512 + ch * 128;
            const float* q0p = qs + (2 * a_) * 128;
            const float* q1p = qs + (2 * a_ + 1) * 128;
#pragma unroll 4
            for (int l = 0; l < 128; l++) {
                float q0 = q0p[l], q1 = q1p[l], k0 = k0p[l], k1 = k1p[l];
                ga00 += q0 * k0; ga01 += q0 * k1; ga10 += q1 * k0; ga11 += q1 * k1;
            }
        }
        float* gp = g_gramp + (size_t)(g * STRIPS + strip) * 1024;
        gp[(2 * a_) * 32 + 2 * b_]     = ga00;
        gp[(2 * a_) * 32 + 2 * b_ + 1] = ga01;
        gp[(2 * a_ + 1) * 32 + 2 * b_]     = ga10;
        gp[(2 * a_ + 1) * 32 + 2 * b_ + 1] = ga11;
#pragma unroll
        for (int m = 0; m < 4; m++) {
            int j = w * 4 + m;
            float s = 0.f;
            for (int t = 0; t < 16; t++) { float v = zs[j * 512 + lane + 32 * t]; s += v * v; }
#pragma unroll
            for (int off = 16; off > 0; off >>= 1) s += __shfl_down_sync(0xffffffffu, s, off);
            if (lane == 0) g_ksqp[(g * STRIPS + strip) * 32 + j] = s;
        }
    }
}

// ============================================================================
// Attention mix (256 threads): S = A · V per head + pooled partials.
// ============================================================================
__global__ void __launch_bounds__(256, 1) attnmix_k(
    const float* __restrict__ V, float* __restrict__ S)
{
    __shared__ float Ast[1024];
    __shared__ float outws[256];
    const int strip = blockIdx.x, h = blockIdx.y;
    const int tid = threadIdx.x;
    for (int i = tid; i < 1024; i += 256) Ast[i] = g_attn[h * 1024 + i];
    __syncthreads();
    const int w = tid >> 5, lane = tid & 31;
    float osum[32];
#pragma unroll
    for (int c = 0; c < 32; c++) osum[c] = 0.f;
    for (int ph = 0; ph < 2; ph++) {
        int p = strip * 512 + ph * 256 + tid;
        float acc[32];
#pragma unroll
        for (int c = 0; c < 32; c++) acc[c] = 0.f;
#pragma unroll 4
        for (int d = 0; d < 32; d++) {
            float vv = __ldg(V + (size_t)(h * 32 + d) * HW + p);
            const float4* ar = (const float4*)(Ast + d * 32);
#pragma unroll
            for (int q = 0; q < 8; q++) {
                float4 a4 = ar[q];
                acc[4 * q + 0] += a4.x * vv; acc[4 * q + 1] += a4.y * vv;
                acc[4 * q + 2] += a4.z * vv; acc[4 * q + 3] += a4.w * vv;
            }
        }
#pragma unroll
        for (int c = 0; c < 32; c++) {
            S[(size_t)(h * 32 + c) * HW + p] = acc[c];
            float v = acc[c];
#pragma unroll
            for (int off = 16; off > 0; off >>= 1) v += __shfl_down_sync(0xffffffffu, v, off);
            if (lane == 0) osum[c] += v;
        }
    }
    if (lane == 0)
        for (int c = 0; c < 32; c++) outws[w * 32 + c] = osum[c];
    __syncthreads();
    if (tid < 32) {
        float s = 0.f;
        for (int w2 = 0; w2 < 8; w2++) s += outws[w2 * 32 + tid];
        g_outsump[(h * STRIPS + strip) * 32 + tid] = s;
    }
}

// ============================================================================
// Conv branch from stored V (256 threads).
// EP 0: avg/max maps. EP 1: gate into S in place.
// ============================================================================
template<int EP>
__global__ void __launch_bounds__(256, 1) convV_k(
    const float* __restrict__ V, const float* __restrict__ wdc,
    const float* __restrict__ bdc, const float* __restrict__ lnw,
    const float* __restrict__ lnb, float* __restrict__ S)
{
    extern __shared__ float sm[];
    float* cxs  = sm;               // 24576
    float* Vg   = cxs + 24576;      // 12288 : 32ch x 384px
    float* w9b  = Vg + 12288;       // 288
    float* mus  = w9b + 288;        // 128
    float* rss  = mus + 128;        // 128
    float* lnws = rss + 128;        // 192
    float* lnbs = lnws + 192;       // 192
    float* bds  = lnbs + 192;       // 192

    const int tid = threadIdx.x;
    const int R = blockIdx.x;
    if (tid < C) { lnws[tid] = lnw[tid]; lnbs[tid] = lnb[tid]; bds[tid] = bdc[tid]; }

    for (int grp = 0; grp < 6; grp++) {
        __syncthreads();
        for (int i = tid; i < 288; i += 256) w9b[i] = wdc[(grp * 32) * 9 + i];
        for (int idx = tid; idx < 32 * 384; idx += 256) {
            int ch = idx / 384, p = idx % 384, r = p >> 7, xc = p & 127;
            int vrow = R - 1 + r;
            Vg[idx] = (vrow >= 0 && vrow < IMG)
                ? __ldg(V + (size_t)(grp * 32 + ch) * HW + vrow * IMG + xc) : 0.f;
        }
        __syncthreads();
        for (int idx = tid; idx < 32 * 128; idx += 256) {
            int ch = idx >> 7, xc = idx & 127;
            const float* vr = Vg + ch * 384;
            const float* w9 = w9b + ch * 9;
            float a = bds[grp * 32 + ch];
#pragma unroll
            for (int dy = 0; dy < 3; dy++) {
                int base = dy * 128 + xc;
                if (xc > 0)   a += w9[dy * 3 + 0] * vr[base - 1];
                              a += w9[dy * 3 + 1] * vr[base];
                if (xc < 127) a += w9[dy * 3 + 2] * vr[base + 1];
            }
            cxs[(grp * 32 + ch) * 128 + xc] = a;
        }
    }
    __syncthreads();
    if (tid < 128) {
        float s = 0.f, s2 = 0.f;
        for (int c = 0; c < C; c++) { float v = cxs[c * 128 + tid]; s += v; s2 += v * v; }
        float mu = s * (1.f / C);
        float var = s2 * (1.f / C) - mu * mu;
        mus[tid] = mu; rss[tid] = rsqrtf(var + 1e-5f);
    }
    __syncthreads();

    if (EP == 0) {
        for (int idx = tid; idx < C * 128; idx += 256) {
            int c = idx >> 7, xc = idx & 127;
            float v = (cxs[idx] - mus[xc]) * rss[xc] * lnws[c] + lnbs[c];
            cxs[idx] = gelu_f(v);
        }
        __syncthreads();
        if (tid < 128) {
            float s = 0.f, mx = -1e30f;
            for (int c = 0; c < C; c++) { float v = cxs[c * 128 + tid]; s += v; mx = fmaxf(mx, v); }
            g_sm[R * 128 + tid]      = s * (1.f / C);
            g_sm[HW + R * 128 + tid] = mx;
        }
    } else {
        for (int idx = tid; idx < C * 128; idx += 256) {
            int c = idx >> 7, xc = idx & 127;
            float v = (cxs[idx] - mus[xc]) * rss[xc] * lnws[c] + lnbs[c];
            float gel = gelu_f(v);
            size_t gi = (size_t)c * HW + R * 128 + xc;
            S[gi] = S[gi] * g_sigsp[R * 128 + xc] + gel * g_sigcm[c];
        }
    }
}

// ------------- in-place channel projection (256 threads) -------------------
__global__ void __launch_bounds__(256, 1) proj_k(
    const float* __restrict__ wproj, float* __restrict__ S)
{
    extern __shared__ float sm[];
    float* Ss  = sm;                 // 24576
    float* Wgt = Ss + 24576;         // 6144

    const int tid = threadIdx.x;
    const int chunk = blockIdx.x;
    for (int i = tid; i < C * 128; i += 256) {
        int c = i >> 7, l = i & 127;
        Ss[i] = S[(size_t)c * HW + chunk * 128 + l];
    }
    for (int og = 0; og < 6; og++) {
        __syncthreads();
        for (int i = tid; i < 6144; i += 256) {
            int c = i >> 5, j = i & 31;
            Wgt[c * 32 + j] = wproj[(size_t)(og * 32 + j) * C + c];
        }
        __syncthreads();
        int px = tid & 127, oh = tid >> 7;
        float acc[16];
#pragma unroll
        for (int j = 0; j < 16; j++) acc[j] = 0.f;
#pragma unroll 4
        for (int c = 0; c < C; c++) {
            float sval = Ss[c * 128 + px];
            const float4* wr = (const float4*)(Wgt + c * 32 + oh * 16);
            float4 w0 = wr[0], w1 = wr[1], w2 = wr[2], w3 = wr[3];
            acc[0]  += w0.x * sval; acc[1]  += w0.y * sval;
            acc[2]  += w0.z * sval; acc[3]  += w0.w * sval;
            acc[4]  += w1.x * sval; acc[5]  += w1.y * sval;
            acc[6]  += w1.z * sval; acc[7]  += w1.w * sval;
            acc[8]  += w2.x * sval; acc[9]  += w2.y * sval;
            acc[10] += w2.z * sval; acc[11] += w2.w * sval;
            acc[12] += w3.x * sval; acc[13] += w3.y * sval;
            acc[14] += w3.z * sval; acc[15] += w3.w * sval;
        }
#pragma unroll
        for (int j = 0; j < 16; j++)
            S[(size_t)(og * 32 + oh * 16 + j) * HW + chunk * 128 + px] = acc[j];
    }
}

// ---------------- small kernels --------------------------------------------
__global__ void normfin_k()
{
    int tid = threadIdx.x;
    int g = tid >> 5, j = tid & 31;
    float qs = 0.f, ks = 0.f;
    for (int s = 0; s < STRIPS; s++) {
        qs += g_qsqp[(g * STRIPS + s) * 32 + j];
        ks += g_ksqp[(g * STRIPS + s) * 32 + j];
    }
    g_qn[tid] = fmaxf(sqrtf(qs), 1e-12f);
    g_kn[tid] = fmaxf(sqrtf(ks), 1e-12f);
}

__global__ void softmax_k()
{
    int h = blockIdx.x;
    int warp = threadIdx.x >> 5, lane = threadIdx.x & 31;
    for (int c = warp; c < 32; c += 8) {
        int d = lane;
        float v = 0.f;
        for (int s = 0; s < STRIPS; s++)
            v += g_gramp[(size_t)(h * STRIPS + s) * 1024 + c * 32 + d];
        v = v / (g_qn[h * CHD + c] * g_kn[h * CHD + d]) * 0.17677669529663687f;
        float m = v;
#pragma unroll
        for (int o = 16; o > 0; o >>= 1) m = fmaxf(m, __shfl_xor_sync(0xffffffffu, m, o));
        float e = expf(v - m);
        float sum = e;
#pragma unroll
        for (int o = 16; o > 0; o >>= 1) sum += __shfl_xor_sync(0xffffffffu, sum, o);
        g_attn[h * 1024 + d * 32 + c] = e / sum;   // transposed [d][c]
    }
}

__global__ void poolmlp_k(const float* __restrict__ w1, const float* __restrict__ b1,
                          const float* __restrict__ w2, const float* __restrict__ b2)
{
    __shared__ float pl[C], hid[24];
    int tid = threadIdx.x;
    {
        int g = tid >> 5, j = tid & 31;
        float s = 0.f;
        for (int st = 0; st < STRIPS; st++) s += g_outsump[(g * STRIPS + st) * 32 + j];
        pl[tid] = s * (1.f / HW);
    }
    __syncthreads();
    if (tid < 24) {
        float a = b1[tid];
        for (int c = 0; c < C; c++) a += w1[tid * C + c] * pl[c];
        hid[tid] = gelu_f(a);
    }
    __syncthreads();
    float a = b2[tid];
#pragma unroll
    for (int j = 0; j < 24; j++) a += w2[tid * 24 + j] * hid[j];
    g_sigcm[tid] = 1.f / (1.f + expf(-a));
}

__global__ void spatial_k(const float* __restrict__ wsi, const float* __restrict__ bsi)
{
    __shared__ float w[98];
    int tid = threadIdx.x;
    if (tid < 98) w[tid] = wsi[tid];
    __syncthreads();
    int pixel = blockIdx.x * 256 + tid;
    int y = pixel >> 7, xcol = pixel & 127;
    float acc = bsi[0];
#pragma unroll
    for (int cc = 0; cc < 2; cc++) {
        const float* sp = g_sm + (size_t)cc * HW;
        const float* wp = w + cc * 49;
        for (int ky = 0; ky < 7; ky++) {
            int yy = y + ky - 3;
            if (yy < 0 || yy >= IMG) continue;
            for (int kx = 0; kx < 7; kx++) {
                int xx = xcol + kx - 3;
                if (xx < 0 || xx >= IMG) continue;
                acc += wp[ky * 7 + kx] * sp[yy * IMG + xx];
            }
        }
    }
    g_sigsp[pixel] = 1.f / (1.f + expf(-acc));
}

// ---------------- launch ---------------------------------------------------
extern "C" void kernel_launch(void* const* d_in, const int* in_sizes, int n_in,
                              void* d_out, int out_size)
{
    (void)in_sizes; (void)n_in; (void)out_size;
    const float* x       = (const float*)d_in[0];
    const float* w_qkv   = (const float*)d_in[1];
    const float* w_dw    = (const float*)d_in[2];
    const float* w_dconv = (const float*)d_in[3];
    const float* b_dconv = (const float*)d_in[4];
    const float* ln_w    = (const float*)d_in[5];
    const float* ln_b    = (const float*)d_in[6];
    const float* w_ci1   = (const float*)d_in[7];
    const float* b_ci1   = (const float*)d_in[8];
    const float* w_ci2   = (const float*)d_in[9];
    const float* b_ci2   = (const float*)d_in[10];
    const float* w_si    = (const float*)d_in[11];
    const float* b_si    = (const float*)d_in[12];
    const float* w_proj  = (const float*)d_in[13];
    float* out = (float*)d_out;

    const size_t smF  = (6144 + 24576 + 24576 + 288) * 4;   // 222336 B
    const size_t smCV = (24576 + 12288 + 288 + 128 + 128 + 192 + 192 + 192) * 4;
    const size_t smPJ = (24576 + 6144) * 4;
    cudaFuncSetAttribute(fused_k<0>, cudaFuncAttributeMaxDynamicSharedMemorySize, (int)smF);
    cudaFuncSetAttribute(fused_k<1>, cudaFuncAttributeMaxDynamicSharedMemorySize, (int)smF);
    cudaFuncSetAttribute(fused_k<3>, cudaFuncAttributeMaxDynamicSharedMemorySize, (int)smF);
    cudaFuncSetAttribute(convV_k<0>, cudaFuncAttributeMaxDynamicSharedMemorySize, (int)smCV);
    cudaFuncSetAttribute(convV_k<1>, cudaFuncAttributeMaxDynamicSharedMemorySize, (int)smCV);
    cudaFuncSetAttribute(proj_k,     cudaFuncAttributeMaxDynamicSharedMemorySize, (int)smPJ);

    float* V = nullptr;
    (void)cudaGetSymbolAddress((void**)&V, g_V);

    for (int b = 0; b < BATCH; b++) {
        const float* xb = x + (size_t)b * C * HW;
        float* S = out + (size_t)b * C * HW;

        fused_k<0><<<dim3(STRIPS, NH), 256, smF>>>(xb, w_qkv, w_dw, S);      // q -> S
        fused_k<1><<<dim3(STRIPS, NH), 256, smF>>>(xb, w_qkv, w_dw, S);      // Gram
        normfin_k<<<1, C>>>();
        softmax_k<<<NH, 256>>>();

        fused_k<3><<<dim3(STRIPS, NH), 256, smF>>>(xb, w_qkv, w_dw, V);      // v -> V
        attnmix_k<<<dim3(STRIPS, NH), 256>>>(V, S);                          // out -> S
        poolmlp_k<<<1, C>>>(w_ci1, b_ci1, w_ci2, b_ci2);
        convV_k<0><<<IMG, 256, smCV>>>(V, w_dconv, b_dconv, ln_w, ln_b, S);  // maps
        spatial_k<<<HW / 256, 256>>>(w_si, b_si);
        convV_k<1><<<IMG, 256, smCV>>>(V, w_dconv, b_dconv, ln_w, ln_b, S);  // gate
        proj_k<<<IMG, 256, smPJ>>>(w_proj, S);                               // final
    }
}